// round 8
// baseline (speedup 1.0000x reference)
#include <cuda_runtime.h>
#include <cuda_bf16.h>
#include <cstdint>
#include <float.h>

// ---------------------------------------------------------------- problem dims
#define B_  32
#define D_  256
#define K_  8192
#define HW  1024
#define N_  32768
#define OUT_ELEMS 8388608
#define LOSS_OFF  OUT_ELEMS
#define IDX_OFF   (OUT_ELEMS + 1)

// ---------------------------------------------------------------- GEMM tiling
#define NCHUNK 64                    // 64 chunks of 128 codes
#define AS_STRIDE 264                // bf16 elems per A smem row (256 + 8 pad)
#define BS_STRIDE 136                // bf16 elems per B smem row (128 + 8 pad)
#define SM_A 0
#define SM_B (128 * AS_STRIDE * 2)   // 67584
#define BUFB (256 * BS_STRIDE * 2)   // 69632
#define SM_TOTAL (SM_B + 2 * BUFB)   // 206848

// ---------------------------------------------------------------- scratch
__device__ __align__(16) float g_enorm[K_];
__device__ __align__(16) int   g_idx[N_];
__device__ __align__(16) float g_part[1024];
__device__ __align__(16) int   g_top4[N_ * 4];
__device__ __align__(16) __nv_bfloat16 g_latT[(size_t)N_ * D_];   // [n][d] row-major
__device__ __align__(16) __nv_bfloat16 g_embBf[(size_t)D_ * K_];  // [d][k] row-major
__device__ __align__(16) float g_embT[(size_t)K_ * D_];           // [k][d] fp32

// ---------------------------------------------------------------- helpers
__device__ __forceinline__ uint32_t smem_u32(const void* p) {
    return (uint32_t)__cvta_generic_to_shared(p);
}
__device__ __forceinline__ void cp_async16(uint32_t dst, const void* src) {
    asm volatile("cp.async.cg.shared.global [%0], [%1], 16;" :: "r"(dst), "l"(src));
}
__device__ __forceinline__ void ldsm_x4(uint32_t* r, uint32_t addr) {
    asm volatile("ldmatrix.sync.aligned.m8n8.x4.shared.b16 {%0,%1,%2,%3}, [%4];"
                 : "=r"(r[0]), "=r"(r[1]), "=r"(r[2]), "=r"(r[3]) : "r"(addr));
}
__device__ __forceinline__ void ldsm_x4_t(uint32_t* r, uint32_t addr) {
    asm volatile("ldmatrix.sync.aligned.m8n8.x4.trans.shared.b16 {%0,%1,%2,%3}, [%4];"
                 : "=r"(r[0]), "=r"(r[1]), "=r"(r[2]), "=r"(r[3]) : "r"(addr));
}
__device__ __forceinline__ void mma_bf16(float* c, const uint32_t* a, uint32_t b0, uint32_t b1) {
    asm volatile(
        "mma.sync.aligned.m16n8k16.row.col.f32.bf16.bf16.f32 "
        "{%0,%1,%2,%3}, {%4,%5,%6,%7}, {%8,%9}, {%0,%1,%2,%3};"
        : "+f"(c[0]), "+f"(c[1]), "+f"(c[2]), "+f"(c[3])
        : "r"(a[0]), "r"(a[1]), "r"(a[2]), "r"(a[3]), "r"(b0), "r"(b1));
}

// ---------------------------------------------------------------- kernel 1: enorm
__global__ void enorm_kernel(const float* __restrict__ emb) {
    int k = blockIdx.x * blockDim.x + threadIdx.x;
    float s = 0.f;
#pragma unroll 8
    for (int d = 0; d < D_; ++d) {
        float v = emb[(size_t)d * K_ + k];
        s = fmaf(v, v, s);
    }
    g_enorm[k] = s;
}

// ---------------------------------------------------------------- kernel 2: latents -> bf16 [n][d]
__global__ void latconv_kernel(const float* __restrict__ lat) {
    __shared__ float t[32][33];
    int b = blockIdx.z, hw0 = blockIdx.x * 32, d0 = blockIdx.y * 32;
    t[threadIdx.y][threadIdx.x] =
        lat[((size_t)b * D_ + d0 + threadIdx.y) * HW + hw0 + threadIdx.x];
    __syncthreads();
    g_latT[((size_t)(b * HW + hw0 + threadIdx.y)) * D_ + d0 + threadIdx.x] =
        __float2bfloat16(t[threadIdx.x][threadIdx.y]);
}

// ---------------------------------------------------------------- kernel 3: embeddings -> bf16 [d][k]
__global__ void embconv_kernel(const float* __restrict__ emb) {
    size_t i = (size_t)blockIdx.x * blockDim.x + threadIdx.x;   // over D_*K_/4
    float4 v = reinterpret_cast<const float4*>(emb)[i];
    __nv_bfloat162 lo = __floats2bfloat162_rn(v.x, v.y);
    __nv_bfloat162 hi = __floats2bfloat162_rn(v.z, v.w);
    uint2 pk;
    pk.x = *reinterpret_cast<uint32_t*>(&lo);
    pk.y = *reinterpret_cast<uint32_t*>(&hi);
    reinterpret_cast<uint2*>(g_embBf)[i] = pk;
}

// ---------------------------------------------------------------- kernel 4: embeddings -> fp32 [k][d] (rescore + gather)
__global__ void embT_kernel(const float* __restrict__ emb) {
    __shared__ float t[32][33];
    int kb = blockIdx.x * 32, db = blockIdx.y * 32;
    t[threadIdx.y][threadIdx.x] = emb[(size_t)(db + threadIdx.y) * K_ + kb + threadIdx.x];
    __syncthreads();
    g_embT[(size_t)(kb + threadIdx.y) * D_ + db + threadIdx.x] = t[threadIdx.x][threadIdx.y];
}

// ---------------------------------------------------------------- kernel 5: bf16 mma.sync GEMM + per-row candidates
__global__ __launch_bounds__(256, 1)
void vq_mma_kernel() {
    extern __shared__ char smem[];
    const uint32_t sb = smem_u32(smem);
    const int tid = threadIdx.x, lane = tid & 31, wid = tid >> 5;
    const int wm = wid & 1;        // 0-1: 64-row half
    const int wn = wid >> 1;       // 0-3: 32-col quarter

    // preload A tile (128 x 256 bf16, padded rows) + B chunk 0, one group
    {
        const char* at = (const char*)(g_latT + (size_t)blockIdx.x * 128 * D_);
        for (int i = tid; i < 4096; i += 256) {
            int r = i >> 5, s = i & 31;
            cp_async16(sb + SM_A + r * (AS_STRIDE * 2) + s * 16, at + r * 512 + s * 16);
        }
        const char* bt = (const char*)g_embBf;
        for (int i = tid; i < 4096; i += 256) {
            int r = i >> 4, s = i & 15;
            cp_async16(sb + SM_B + r * (BS_STRIDE * 2) + s * 16,
                       bt + (size_t)r * (K_ * 2) + s * 16);
        }
        asm volatile("cp.async.commit_group;" ::: "memory");
    }

    // per-lane ldmatrix base addresses
    uint32_t a_addr[4];
#pragma unroll
    for (int mf = 0; mf < 4; ++mf)
        a_addr[mf] = sb + SM_A + (wm * 64 + mf * 16 + (lane & 15)) * (AS_STRIDE * 2)
                   + (lane >> 4) * 16;
    const uint32_t b_off = (((lane >> 3) & 1) * 8 + (lane & 7)) * (BS_STRIDE * 2)
                         + (wn * 32 + (lane >> 4) * 8) * 2;

    // per-(thread,row) top-2 over this thread's disjoint 512-col subset
    float sv[8][2];
    int   si[8][2];
#pragma unroll
    for (int r = 0; r < 8; ++r) { sv[r][0] = sv[r][1] = FLT_MAX; si[r][0] = si[r][1] = 0; }

    for (int u = 0; u < NCHUNK; ++u) {
        if (u + 1 < NCHUNK) {
            const char* bt = (const char*)g_embBf + (size_t)(u + 1) * 256;
            uint32_t bd = sb + SM_B + ((u + 1) & 1) * BUFB;
            for (int i = tid; i < 4096; i += 256) {
                int r = i >> 4, s = i & 15;
                cp_async16(bd + r * (BS_STRIDE * 2) + s * 16,
                           bt + (size_t)r * (K_ * 2) + s * 16);
            }
            asm volatile("cp.async.commit_group;" ::: "memory");
            asm volatile("cp.async.wait_group 1;" ::: "memory");
        } else {
            asm volatile("cp.async.wait_group 0;" ::: "memory");
        }
        __syncthreads();

        float acc[4][4][4];
#pragma unroll
        for (int mf = 0; mf < 4; ++mf)
#pragma unroll
            for (int nf = 0; nf < 4; ++nf)
#pragma unroll
                for (int q = 0; q < 4; ++q) acc[mf][nf][q] = 0.f;

        const uint32_t bbase = sb + SM_B + (u & 1) * BUFB + b_off;

        // -------- software-pipelined ks loop: LDSM for ks+1 overlaps MMAs of ks
        uint32_t ar[2][4][4], br[2][2][4];
#pragma unroll
        for (int mf = 0; mf < 4; ++mf) ldsm_x4(ar[0][mf], a_addr[mf]);
#pragma unroll
        for (int p = 0; p < 2; ++p) ldsm_x4_t(br[0][p], bbase + p * 32);

#pragma unroll
        for (int ks = 0; ks < 16; ++ks) {
            const int cur = ks & 1, nxt = cur ^ 1;
            if (ks < 15) {
#pragma unroll
                for (int mf = 0; mf < 4; ++mf)
                    ldsm_x4(ar[nxt][mf], a_addr[mf] + (ks + 1) * 32);
#pragma unroll
                for (int p = 0; p < 2; ++p)
                    ldsm_x4_t(br[nxt][p],
                              bbase + (ks + 1) * 16 * (BS_STRIDE * 2) + p * 32);
            }
#pragma unroll
            for (int mf = 0; mf < 4; ++mf)
#pragma unroll
                for (int nf = 0; nf < 4; ++nf)
                    mma_bf16(acc[mf][nf], ar[cur][mf],
                             br[cur][nf >> 1][(nf & 1) * 2],
                             br[cur][nf >> 1][(nf & 1) * 2 + 1]);
        }

        // epilogue: sc = enorm[c] - 2*dot; track top-2 per row subset.
        const int cb0 = (u << 7) + wn * 32 + (lane & 3) * 2;
#pragma unroll
        for (int nf = 0; nf < 4; ++nf) {
            const int c0 = cb0 + nf * 8;
            float2 e = __ldg(reinterpret_cast<const float2*>(&g_enorm[c0]));
#pragma unroll
            for (int mf = 0; mf < 4; ++mf) {
#pragma unroll
                for (int half = 0; half < 2; ++half) {
                    const int rs = mf * 2 + half;
                    float v0 = fmaf(-2.f, acc[mf][nf][half * 2 + 0], e.x);
                    float v1 = fmaf(-2.f, acc[mf][nf][half * 2 + 1], e.y);
                    if (v0 < sv[rs][1]) {
                        if (v0 < sv[rs][0]) { sv[rs][1] = sv[rs][0]; si[rs][1] = si[rs][0];
                                              sv[rs][0] = v0; si[rs][0] = c0; }
                        else                { sv[rs][1] = v0; si[rs][1] = c0; }
                    }
                    if (v1 < sv[rs][1]) {
                        if (v1 < sv[rs][0]) { sv[rs][1] = sv[rs][0]; si[rs][1] = si[rs][0];
                                              sv[rs][0] = v1; si[rs][0] = c0 + 1; }
                        else                { sv[rs][1] = v1; si[rs][1] = c0 + 1; }
                    }
                }
            }
        }
        __syncthreads();   // protect B buffer reuse by next prefetch
    }

    // merge: 16 subsets x top-2 = 32 candidates per row -> top-4
    struct Pair { float v; int i; };
    Pair* pr = reinterpret_cast<Pair*>(smem);   // [128][32], 32KB (A region, done)
    __syncthreads();
#pragma unroll
    for (int rs = 0; rs < 8; ++rs) {
        int r = wm * 64 + (rs >> 1) * 16 + (lane >> 2) + (rs & 1) * 8;
        int sub = wn * 4 + (lane & 3);
        pr[r * 32 + sub * 2 + 0] = { sv[rs][0], si[rs][0] };
        pr[r * 32 + sub * 2 + 1] = { sv[rs][1], si[rs][1] };
    }
    __syncthreads();
    if (tid < 128) {
        float bv[4] = {FLT_MAX, FLT_MAX, FLT_MAX, FLT_MAX};
        int   bi[4] = {0x7fffffff, 0x7fffffff, 0x7fffffff, 0x7fffffff};
        for (int j = 0; j < 32; ++j) {
            float v = pr[tid * 32 + j].v;
            int   i = pr[tid * 32 + j].i;
            if (v < bv[3] || (v == bv[3] && i < bi[3])) {
                if (v < bv[0] || (v == bv[0] && i < bi[0])) {
                    bv[3]=bv[2]; bi[3]=bi[2]; bv[2]=bv[1]; bi[2]=bi[1];
                    bv[1]=bv[0]; bi[1]=bi[0]; bv[0]=v; bi[0]=i;
                } else if (v < bv[1] || (v == bv[1] && i < bi[1])) {
                    bv[3]=bv[2]; bi[3]=bi[2]; bv[2]=bv[1]; bi[2]=bi[1];
                    bv[1]=v; bi[1]=i;
                } else if (v < bv[2] || (v == bv[2] && i < bi[2])) {
                    bv[3]=bv[2]; bi[3]=bi[2]; bv[2]=v; bi[2]=i;
                } else {
                    bv[3]=v; bi[3]=i;
                }
            }
        }
        int row = blockIdx.x * 128 + tid;
#pragma unroll
        for (int s = 0; s < 4; ++s) g_top4[row * 4 + s] = bi[s];
    }
}

// ---------------------------------------------------------------- kernel 6: exact fp32 rescore of top-4
__global__ __launch_bounds__(256)
void rescore_kernel(const float* __restrict__ lat, float* __restrict__ out_idx_f) {
    int row = blockIdx.x * 32 + (threadIdx.x >> 3);
    int l8  = threadIdx.x & 7;
    int b = row >> 10, hw = row & (HW - 1);
    const float* z = lat + (size_t)b * (D_ * HW) + hw;
    int cand[4];
#pragma unroll
    for (int c = 0; c < 4; ++c) cand[c] = g_top4[row * 4 + c];
    float dot[4] = {0.f, 0.f, 0.f, 0.f};
    for (int d = l8; d < D_; d += 8) {
        float zv = z[(size_t)d * HW];
#pragma unroll
        for (int c = 0; c < 4; ++c)
            dot[c] = fmaf(zv, g_embT[(size_t)cand[c] * D_ + d], dot[c]);
    }
#pragma unroll
    for (int c = 0; c < 4; ++c) {
#pragma unroll
        for (int off = 4; off > 0; off >>= 1)
            dot[c] += __shfl_down_sync(0xffffffffu, dot[c], off, 8);
    }
    if (l8 == 0) {
        float bv = FLT_MAX; int bi = 0x7fffffff;
#pragma unroll
        for (int c = 0; c < 4; ++c) {
            float dist = fmaf(-2.f, dot[c], g_enorm[cand[c]]);
            if (dist < bv || (dist == bv && cand[c] < bi)) { bv = dist; bi = cand[c]; }
        }
        g_idx[row] = bi;
        out_idx_f[row] = (float)bi;
    }
}

// ---------------------------------------------------------------- kernel 7: gather + loss, fully coalesced via embT + smem transpose
__global__ __launch_bounds__(256)
void gather_loss_kernel(const float* __restrict__ lat, float* __restrict__ out) {
    __shared__ float tile[32][257];   // [w][d], padded: stride 257 mod 32 = 1
    int bh = blockIdx.x;              // (b,h)
    int b = bh >> 5, h = bh & 31;
    int t = threadIdx.x;

    // load phase: row i's embedding vector, 256 consecutive floats per row
#pragma unroll 4
    for (int i = 0; i < 32; ++i) {
        int idx = g_idx[bh * 32 + i];
        tile[i][t] = g_embT[(size_t)idx * D_ + t];
    }
    __syncthreads();

    // write phase: coalesced over w; fuse squared-error partials
    size_t base = (size_t)b * (D_ * HW) + h * 32;
    int w = t & 31, d0 = t >> 5;
    float lsum = 0.f;
#pragma unroll 4
    for (int i = 0; i < 32; ++i) {
        int d = i * 8 + d0;
        float v = tile[w][d];
        float x = lat[base + (size_t)d * HW + w];
        out[base + (size_t)d * HW + w] = v;
        float df = v - x;
        lsum = fmaf(df, df, lsum);
    }
    __shared__ float red[256];
    red[t] = lsum;
    __syncthreads();
    for (int st = 128; st > 0; st >>= 1) {
        if (t < st) red[t] += red[t + st];
        __syncthreads();
    }
    if (t == 0) g_part[bh] = red[0];
}

// ---------------------------------------------------------------- kernel 8: final loss
__global__ void loss_kernel(float* __restrict__ out_loss) {
    __shared__ float red[1024];
    int t = threadIdx.x;
    red[t] = g_part[t];
    __syncthreads();
    for (int st = 512; st > 0; st >>= 1) {
        if (t < st) red[t] += red[t + st];
        __syncthreads();
    }
    if (t == 0) out_loss[0] = 1.25f * (red[0] / 8388608.0f);
}

// ----------------------------------------------------------------
extern "C" void kernel_launch(void* const* d_in, const int* in_sizes, int n_in,
                              void* d_out, int out_size) {
    const float* lat = (const float*)d_in[0];
    const float* emb = (const float*)d_in[1];
    if (n_in >= 2 && in_sizes[0] == D_ * K_) {   // defensive size-based ident
        lat = (const float*)d_in[1];
        emb = (const float*)d_in[0];
    }
    float* out = (float*)d_out;

    enorm_kernel<<<K_ / 256, 256>>>(emb);
    latconv_kernel<<<dim3(HW / 32, D_ / 32, B_), dim3(32, 32)>>>(lat);
    embconv_kernel<<<(D_ * K_ / 4) / 256, 256>>>(emb);

    // vq_mma is deliberately the 4th launch: ncu's skip window profiles slot 4,
    // and this is the kernel whose roofline we need next round.
    cudaFuncSetAttribute(vq_mma_kernel,
                         cudaFuncAttributeMaxDynamicSharedMemorySize, SM_TOTAL);
    vq_mma_kernel<<<N_ / 128, 256, SM_TOTAL>>>();

    embT_kernel<<<dim3(K_ / 32, D_ / 32), dim3(32, 32)>>>(emb);
    rescore_kernel<<<N_ / 32, 256>>>(lat, out + IDX_OFF);
    gather_loss_kernel<<<B_ * 32, 256>>>(lat, out);
    loss_kernel<<<1, 1024>>>(out + LOSS_OFF);
}